// round 8
// baseline (speedup 1.0000x reference)
#include <cuda_runtime.h>
#include <math.h>

#define N_TOTAL 16384
#define TPB     512
#define GRID    296          // 2 CTAs per SM
#define ROWS    8
#define JV      4
#define EPT     (N_TOTAL / TPB)     // 32
#define PADV    64.0f

__device__ float        g_partial[GRID];
__device__ unsigned int g_arrive = 0;

// ---------------------------------------------------------------------------
// Persistent fused kernel (R7 inner loop, 2 CTAs/SM for latency hiding).
//  phase 1: per-block deterministic compaction of pos/neg into smem (+pads)
//  phase 2: S = sum over padded grid of max(0, 1-p+n) via
//             t = ffma(n, 0.5, ch); m = fmax(t,0); acc = ffma(m, 2.0, acc)
//           (FFMA-imm rt=1 verified in R7; pads contribute exactly 0)
//  phase 3: last block reduces partials in double, divides by npos*nneg
// ---------------------------------------------------------------------------
__global__ __launch_bounds__(TPB, 2)
void fused_kernel(const int* __restrict__ yt, const float* __restrict__ yp,
                  float* __restrict__ out) {
    extern __shared__ float sm[];          // sneg[nneg_pad] then spos[npos_pad]
    __shared__ int    wsum[16];
    __shared__ float  s_red[16];
    __shared__ int    s_amlast;

    const int tid  = threadIdx.x;
    const int lane = tid & 31;
    const int warp = tid >> 5;

    // ---- phase 1a: load 32 contiguous elems/thread, count pos ----
    const int base = tid * EPT;
    int4   tt[EPT / 4];
    float4 vv[EPT / 4];
    int cp = 0;
    #pragma unroll
    for (int k = 0; k < EPT / 4; k++) {
        tt[k] = ((const int4*)yt)[(base >> 2) + k];
        vv[k] = ((const float4*)yp)[(base >> 2) + k];
        cp += (tt[k].x == 1) + (tt[k].y == 1) + (tt[k].z == 1) + (tt[k].w == 1);
    }

    // ---- phase 1b: block exclusive scan ----
    int inc = cp;
    #pragma unroll
    for (int o = 1; o < 32; o <<= 1) {
        int t = __shfl_up_sync(0xffffffffu, inc, o);
        if (lane >= o) inc += t;
    }
    if (lane == 31) wsum[warp] = inc;
    __syncthreads();
    if (warp == 0) {
        int w = (lane < 16) ? wsum[lane] : 0;
        #pragma unroll
        for (int o = 1; o < 16; o <<= 1) {
            int t = __shfl_up_sync(0xffffffffu, w, o);
            if (lane >= o) w += t;
        }
        if (lane < 16) wsum[lane] = w;
    }
    __syncthreads();

    const int excl     = inc - cp + (warp > 0 ? wsum[warp - 1] : 0);
    const int npos     = wsum[15];
    const int nneg     = N_TOTAL - npos;
    const int nneg_pad = (nneg + JV - 1) & ~(JV - 1);
    const int npos_pad = (npos + ROWS - 1) & ~(ROWS - 1);
    float* sneg = sm;
    float* spos = sm + nneg_pad;

    // ---- phase 1c: scatter + finite pads (pads contribute exactly 0) ----
    {
        int po = excl;
        int no = base - excl;
        #pragma unroll
        for (int k = 0; k < EPT / 4; k++) {
            if (tt[k].x == 1) spos[po++] = vv[k].x; else sneg[no++] = vv[k].x;
            if (tt[k].y == 1) spos[po++] = vv[k].y; else sneg[no++] = vv[k].y;
            if (tt[k].z == 1) spos[po++] = vv[k].z; else sneg[no++] = vv[k].z;
            if (tt[k].w == 1) spos[po++] = vv[k].w; else sneg[no++] = vv[k].w;
        }
        for (int j = nneg + tid; j < nneg_pad; j += TPB) sneg[j] = -PADV;
        for (int i = npos + tid; i < npos_pad; i += TPB) spos[i] = 1.0f + PADV;
    }
    __syncthreads();

    // ---- phase 2: scalar FFMA-imm hinge, strided ROWS-groups ----
    float acc[ROWS];
    #pragma unroll
    for (int r = 0; r < ROWS; r++) acc[r] = 0.f;

    for (int r0 = blockIdx.x * ROWS; r0 < npos_pad; r0 += GRID * ROWS) {
        float ch[ROWS];
        #pragma unroll
        for (int r = 0; r < ROWS; r++)
            ch[r] = __fmaf_rn(spos[r0 + r], -0.5f, 0.5f);   // (1-p)/2

        for (int j = tid * JV; j < nneg_pad; j += TPB * JV) {
            const float4 n4 = *reinterpret_cast<const float4*>(sneg + j);
            #pragma unroll
            for (int r = 0; r < ROWS; r++) {
                const float t0 = __fmaf_rn(n4.x, 0.5f, ch[r]);
                const float t1 = __fmaf_rn(n4.y, 0.5f, ch[r]);
                const float t2 = __fmaf_rn(n4.z, 0.5f, ch[r]);
                const float t3 = __fmaf_rn(n4.w, 0.5f, ch[r]);
                const float m0 = fmaxf(t0, 0.0f);
                const float m1 = fmaxf(t1, 0.0f);
                const float m2 = fmaxf(t2, 0.0f);
                const float m3 = fmaxf(t3, 0.0f);
                acc[r] = __fmaf_rn(m0, 2.0f, acc[r]);
                acc[r] = __fmaf_rn(m1, 2.0f, acc[r]);
                acc[r] = __fmaf_rn(m2, 2.0f, acc[r]);
                acc[r] = __fmaf_rn(m3, 2.0f, acc[r]);
            }
        }
    }

    float accv = 0.f;
    #pragma unroll
    for (int r = 0; r < ROWS; r += 2) accv += acc[r] + acc[r + 1];

    // ---- block reduction (fixed order) ----
    #pragma unroll
    for (int o = 16; o > 0; o >>= 1)
        accv += __shfl_down_sync(0xffffffffu, accv, o);
    if (lane == 0) s_red[warp] = accv;
    __syncthreads();
    if (warp == 0) {
        float w = (lane < 16) ? s_red[lane] : 0.f;
        #pragma unroll
        for (int o = 16; o > 0; o >>= 1)
            w += __shfl_down_sync(0xffffffffu, w, o);
        if (lane == 0) g_partial[blockIdx.x] = w;
    }

    // ---- phase 3: last block finalizes (double, fixed order) ----
    if (tid == 0) {
        __threadfence();
        unsigned int prev = atomicAdd(&g_arrive, 1u);
        s_amlast = (prev == GRID - 1);
    }
    __syncthreads();
    if (!s_amlast) return;
    __threadfence();

    if (warp == 0) {
        double S = 0.0;
        for (int i = lane; i < GRID; i += 32) S += (double)g_partial[i];
        #pragma unroll
        for (int o = 16; o > 0; o >>= 1)
            S += __shfl_down_sync(0xffffffffu, S, o);
        if (lane == 0) {
            out[0] = (float)(S / ((double)npos * (double)nneg));
            g_arrive = 0u;    // reset for next graph replay
        }
    }
}

extern "C" void kernel_launch(void* const* d_in, const int* in_sizes, int n_in,
                              void* d_out, int out_size) {
    const int*   yt = (const int*)d_in[0];
    const float* yp = (const float*)d_in[1];

    const int smem_bytes = (N_TOTAL + ROWS + JV) * sizeof(float);   // ~65.6 KB
    cudaFuncSetAttribute(fused_kernel,
                         cudaFuncAttributeMaxDynamicSharedMemorySize, smem_bytes);

    fused_kernel<<<GRID, TPB, smem_bytes>>>(yt, yp, (float*)d_out);
}

// round 9
// speedup vs baseline: 1.2545x; 1.2545x over previous
#include <cuda_runtime.h>
#include <math.h>

#define N_TOTAL 16384
#define TPB     512
#define GRID    148
#define ROWS    8
#define KMAX    17                      // negs per thread: covers nneg <= 8704
#define NNEG_REG (KMAX * TPB)           // 8704
#define EPT     (N_TOTAL / TPB)         // 32
#define PADV    64.0f

__device__ float        g_partial[GRID];
__device__ unsigned int g_arrive = 0;

// ---------------------------------------------------------------------------
// Persistent fused kernel — register-resident negatives.
//  phase 1: per-block deterministic compaction of pos/neg into smem (+pads)
//  phase 2: each thread hoists its 17 negs into registers ONCE; group loop is
//           pure register math:
//             t = ffma(n, 0.5, ch); m = fmax(t,0); acc = ffma(m, 2.0, acc)
//           (FFMA-imm rt=1 verified R7; pads produce t<0 -> exactly 0)
//  phase 3: last block reduces partials in double, divides by npos*nneg
// ---------------------------------------------------------------------------
__global__ __launch_bounds__(TPB, 1)
void fused_kernel(const int* __restrict__ yt, const float* __restrict__ yp,
                  float* __restrict__ out) {
    extern __shared__ float sm[];       // sneg[max(8704,nneg)] then spos[...]
    __shared__ int    wsum[16];
    __shared__ float  s_red[16];
    __shared__ int    s_amlast;

    const int tid  = threadIdx.x;
    const int lane = tid & 31;
    const int warp = tid >> 5;

    // ---- phase 1a: load 32 contiguous elems/thread, count pos ----
    const int base = tid * EPT;
    int4   tt[EPT / 4];
    float4 vv[EPT / 4];
    int cp = 0;
    #pragma unroll
    for (int k = 0; k < EPT / 4; k++) {
        tt[k] = ((const int4*)yt)[(base >> 2) + k];
        vv[k] = ((const float4*)yp)[(base >> 2) + k];
        cp += (tt[k].x == 1) + (tt[k].y == 1) + (tt[k].z == 1) + (tt[k].w == 1);
    }

    // ---- phase 1b: block exclusive scan ----
    int inc = cp;
    #pragma unroll
    for (int o = 1; o < 32; o <<= 1) {
        int t = __shfl_up_sync(0xffffffffu, inc, o);
        if (lane >= o) inc += t;
    }
    if (lane == 31) wsum[warp] = inc;
    __syncthreads();
    if (warp == 0) {
        int w = (lane < 16) ? wsum[lane] : 0;
        #pragma unroll
        for (int o = 1; o < 16; o <<= 1) {
            int t = __shfl_up_sync(0xffffffffu, w, o);
            if (lane >= o) w += t;
        }
        if (lane < 16) wsum[lane] = w;
    }
    __syncthreads();

    const int excl     = inc - cp + (warp > 0 ? wsum[warp - 1] : 0);
    const int npos     = wsum[15];
    const int nneg     = N_TOTAL - npos;
    const int nneg_reg = (nneg > NNEG_REG) ? nneg : NNEG_REG;  // smem split pt
    const int npos_pad = (npos + ROWS - 1) & ~(ROWS - 1);
    float* sneg = sm;
    float* spos = sm + nneg_reg;

    // ---- phase 1c: scatter + finite pads (pads contribute exactly 0) ----
    {
        int po = excl;
        int no = base - excl;
        #pragma unroll
        for (int k = 0; k < EPT / 4; k++) {
            if (tt[k].x == 1) spos[po++] = vv[k].x; else sneg[no++] = vv[k].x;
            if (tt[k].y == 1) spos[po++] = vv[k].y; else sneg[no++] = vv[k].y;
            if (tt[k].z == 1) spos[po++] = vv[k].z; else sneg[no++] = vv[k].z;
            if (tt[k].w == 1) spos[po++] = vv[k].w; else sneg[no++] = vv[k].w;
        }
        for (int j = nneg + tid; j < NNEG_REG; j += TPB) sneg[j] = -PADV;
        for (int i = npos + tid; i < npos_pad; i += TPB) spos[i] = 1.0f + PADV;
    }
    __syncthreads();

    // ---- phase 2a: hoist this thread's negs into registers (once) ----
    float nr[KMAX];
    #pragma unroll
    for (int k = 0; k < KMAX; k++)
        nr[k] = sneg[tid + k * TPB];          // conflict-free scalar LDS

    const bool overflow = (nneg > NNEG_REG);  // never in practice (>6 sigma)

    // ---- phase 2b: group loop — pure register math ----
    float acc[ROWS];
    #pragma unroll
    for (int r = 0; r < ROWS; r++) acc[r] = 0.f;

    for (int r0 = blockIdx.x * ROWS; r0 < npos_pad; r0 += GRID * ROWS) {
        float ch[ROWS];
        #pragma unroll
        for (int r = 0; r < ROWS; r++)
            ch[r] = __fmaf_rn(spos[r0 + r], -0.5f, 0.5f);   // (1-p)/2

        #pragma unroll
        for (int k = 0; k < KMAX; k++) {
            const float nk = nr[k];
            #pragma unroll
            for (int r = 0; r < ROWS; r++) {
                const float t = __fmaf_rn(nk, 0.5f, ch[r]);
                const float m = fmaxf(t, 0.0f);
                acc[r] = __fmaf_rn(m, 2.0f, acc[r]);
            }
        }

        if (overflow) {                        // correctness-only fallback
            for (int j = NNEG_REG + tid; j < nneg; j += TPB) {
                const float nk = sneg[j];
                #pragma unroll
                for (int r = 0; r < ROWS; r++) {
                    const float t = __fmaf_rn(nk, 0.5f, ch[r]);
                    acc[r] = __fmaf_rn(fmaxf(t, 0.0f), 2.0f, acc[r]);
                }
            }
        }
    }

    float accv = 0.f;
    #pragma unroll
    for (int r = 0; r < ROWS; r += 2) accv += acc[r] + acc[r + 1];

    // ---- block reduction (fixed order) ----
    #pragma unroll
    for (int o = 16; o > 0; o >>= 1)
        accv += __shfl_down_sync(0xffffffffu, accv, o);
    if (lane == 0) s_red[warp] = accv;
    __syncthreads();
    if (warp == 0) {
        float w = (lane < 16) ? s_red[lane] : 0.f;
        #pragma unroll
        for (int o = 16; o > 0; o >>= 1)
            w += __shfl_down_sync(0xffffffffu, w, o);
        if (lane == 0) g_partial[blockIdx.x] = w;
    }

    // ---- phase 3: last block finalizes (double, fixed order) ----
    if (tid == 0) {
        __threadfence();
        unsigned int prev = atomicAdd(&g_arrive, 1u);
        s_amlast = (prev == GRID - 1);
    }
    __syncthreads();
    if (!s_amlast) return;
    __threadfence();

    if (warp == 0) {
        double S = 0.0;
        for (int i = lane; i < GRID; i += 32) S += (double)g_partial[i];
        #pragma unroll
        for (int o = 16; o > 0; o >>= 1)
            S += __shfl_down_sync(0xffffffffu, S, o);
        if (lane == 0) {
            out[0] = (float)(S / ((double)npos * (double)nneg));
            g_arrive = 0u;    // reset for next graph replay
        }
    }
}

extern "C" void kernel_launch(void* const* d_in, const int* in_sizes, int n_in,
                              void* d_out, int out_size) {
    const int*   yt = (const int*)d_in[0];
    const float* yp = (const float*)d_in[1];

    // worst case: nneg region max(8704, N) + pos region N  (fits 228KB)
    const int smem_bytes = (NNEG_REG + N_TOTAL + ROWS + 8) * sizeof(float);
    cudaFuncSetAttribute(fused_kernel,
                         cudaFuncAttributeMaxDynamicSharedMemorySize, smem_bytes);

    fused_kernel<<<GRID, TPB, smem_bytes>>>(yt, yp, (float*)d_out);
}

// round 10
// speedup vs baseline: 1.5328x; 1.2218x over previous
#include <cuda_runtime.h>
#include <math.h>

#define N_TOTAL 16384
#define TPB     1024
#define GRID    148
#define ROWS    8
#define KFULL   8                        // unrolled negs/thread (8192 total)
#define KMAX    9                        // +1 guarded slice -> nneg <= 9216
#define NNEG_REG (KMAX * TPB)            // 9216
#define EPT     (N_TOTAL / TPB)          // 16
#define PADV    64.0f

__device__ float        g_partial[GRID];
__device__ unsigned int g_arrive = 0;

// ---------------------------------------------------------------------------
// Persistent fused kernel — TPB=1024 issue density x R7 lean inner op
//                           x register-resident negs (9 regs/thread).
//  phase 1: per-block deterministic compaction of pos/neg into smem (+pads)
//  phase 2: thread hoists its <=9 negs into registers once; group loop is
//           pure register math:
//             t = ffma(n, 0.5, ch); m = fmax(t,0); acc = ffma(m, 2.0, acc)
//           (FFMA-imm rt=1 verified R7; pads give t<0 -> contribute exactly 0)
//  phase 3: last block reduces partials in double, divides by npos*nneg
// ---------------------------------------------------------------------------
__global__ __launch_bounds__(TPB, 1)
void fused_kernel(const int* __restrict__ yt, const float* __restrict__ yp,
                  float* __restrict__ out) {
    extern __shared__ float sm[];        // sneg[max(9216,nneg)] then spos[...]
    __shared__ int    wsum[32];
    __shared__ float  s_red[32];
    __shared__ int    s_amlast;

    const int tid  = threadIdx.x;
    const int lane = tid & 31;
    const int warp = tid >> 5;

    // ---- phase 1a: load 16 contiguous elems/thread, count pos ----
    const int base = tid * EPT;
    int4   tt[EPT / 4];
    float4 vv[EPT / 4];
    int cp = 0;
    #pragma unroll
    for (int k = 0; k < EPT / 4; k++) {
        tt[k] = ((const int4*)yt)[(base >> 2) + k];
        vv[k] = ((const float4*)yp)[(base >> 2) + k];
        cp += (tt[k].x == 1) + (tt[k].y == 1) + (tt[k].z == 1) + (tt[k].w == 1);
    }

    // ---- phase 1b: block exclusive scan ----
    int inc = cp;
    #pragma unroll
    for (int o = 1; o < 32; o <<= 1) {
        int t = __shfl_up_sync(0xffffffffu, inc, o);
        if (lane >= o) inc += t;
    }
    if (lane == 31) wsum[warp] = inc;
    __syncthreads();
    if (warp == 0) {
        int w = wsum[lane];
        #pragma unroll
        for (int o = 1; o < 32; o <<= 1) {
            int t = __shfl_up_sync(0xffffffffu, w, o);
            if (lane >= o) w += t;
        }
        wsum[lane] = w;
    }
    __syncthreads();

    const int excl     = inc - cp + (warp > 0 ? wsum[warp - 1] : 0);
    const int npos     = wsum[31];
    const int nneg     = N_TOTAL - npos;
    const int nneg_reg = (nneg > NNEG_REG) ? nneg : NNEG_REG;
    const int npos_pad = (npos + ROWS - 1) & ~(ROWS - 1);
    float* sneg = sm;
    float* spos = sm + nneg_reg;

    // ---- phase 1c: scatter + finite pads (pads contribute exactly 0) ----
    {
        int po = excl;
        int no = base - excl;
        #pragma unroll
        for (int k = 0; k < EPT / 4; k++) {
            if (tt[k].x == 1) spos[po++] = vv[k].x; else sneg[no++] = vv[k].x;
            if (tt[k].y == 1) spos[po++] = vv[k].y; else sneg[no++] = vv[k].y;
            if (tt[k].z == 1) spos[po++] = vv[k].z; else sneg[no++] = vv[k].z;
            if (tt[k].w == 1) spos[po++] = vv[k].w; else sneg[no++] = vv[k].w;
        }
        for (int j = nneg + tid; j < NNEG_REG; j += TPB) sneg[j] = -PADV;
        for (int i = npos + tid; i < npos_pad; i += TPB) spos[i] = 1.0f + PADV;
    }
    __syncthreads();

    // ---- phase 2a: hoist this thread's negs into registers (once) ----
    float nr[KMAX];
    #pragma unroll
    for (int k = 0; k < KMAX; k++)
        nr[k] = sneg[tid + k * TPB];            // conflict-free scalar LDS

    const bool has_k8    = (nneg > KFULL * TPB);   // uniform, data-dependent
    const bool overflow  = (nneg > NNEG_REG);      // never in practice

    // ---- phase 2b: group loop — pure register math ----
    float acc[ROWS];
    #pragma unroll
    for (int r = 0; r < ROWS; r++) acc[r] = 0.f;

    for (int r0 = blockIdx.x * ROWS; r0 < npos_pad; r0 += GRID * ROWS) {
        float ch[ROWS];
        #pragma unroll
        for (int r = 0; r < ROWS; r++)
            ch[r] = __fmaf_rn(spos[r0 + r], -0.5f, 0.5f);   // (1-p)/2

        #pragma unroll
        for (int k = 0; k < KFULL; k++) {
            const float nk = nr[k];
            #pragma unroll
            for (int r = 0; r < ROWS; r++) {
                const float t = __fmaf_rn(nk, 0.5f, ch[r]);
                const float m = fmaxf(t, 0.0f);
                acc[r] = __fmaf_rn(m, 2.0f, acc[r]);
            }
        }
        if (has_k8) {                        // slice 8: only when nneg > 8192
            const float nk = nr[KFULL];
            #pragma unroll
            for (int r = 0; r < ROWS; r++) {
                const float t = __fmaf_rn(nk, 0.5f, ch[r]);
                acc[r] = __fmaf_rn(fmaxf(t, 0.0f), 2.0f, acc[r]);
            }
        }
        if (overflow) {                      // correctness-only fallback
            for (int j = NNEG_REG + tid; j < nneg; j += TPB) {
                const float nk = sneg[j];
                #pragma unroll
                for (int r = 0; r < ROWS; r++) {
                    const float t = __fmaf_rn(nk, 0.5f, ch[r]);
                    acc[r] = __fmaf_rn(fmaxf(t, 0.0f), 2.0f, acc[r]);
                }
            }
        }
    }

    float accv = 0.f;
    #pragma unroll
    for (int r = 0; r < ROWS; r += 2) accv += acc[r] + acc[r + 1];

    // ---- block reduction (fixed order) ----
    #pragma unroll
    for (int o = 16; o > 0; o >>= 1)
        accv += __shfl_down_sync(0xffffffffu, accv, o);
    if (lane == 0) s_red[warp] = accv;
    __syncthreads();
    if (warp == 0) {
        float w = s_red[lane];
        #pragma unroll
        for (int o = 16; o > 0; o >>= 1)
            w += __shfl_down_sync(0xffffffffu, w, o);
        if (lane == 0) g_partial[blockIdx.x] = w;
    }

    // ---- phase 3: last block finalizes (double, fixed order) ----
    if (tid == 0) {
        __threadfence();
        unsigned int prev = atomicAdd(&g_arrive, 1u);
        s_amlast = (prev == GRID - 1);
    }
    __syncthreads();
    if (!s_amlast) return;
    __threadfence();

    if (warp == 0) {
        double S = 0.0;
        for (int i = lane; i < GRID; i += 32) S += (double)g_partial[i];
        #pragma unroll
        for (int o = 16; o > 0; o >>= 1)
            S += __shfl_down_sync(0xffffffffu, S, o);
        if (lane == 0) {
            out[0] = (float)(S / ((double)npos * (double)nneg));
            g_arrive = 0u;    // reset for next graph replay
        }
    }
}

extern "C" void kernel_launch(void* const* d_in, const int* in_sizes, int n_in,
                              void* d_out, int out_size) {
    const int*   yt = (const int*)d_in[0];
    const float* yp = (const float*)d_in[1];

    // sneg region max(9216, nneg) + pos region (<= N+ROWS)  -> ~102.6 KB
    const int smem_bytes = (NNEG_REG + N_TOTAL + ROWS + 8) * sizeof(float);
    cudaFuncSetAttribute(fused_kernel,
                         cudaFuncAttributeMaxDynamicSharedMemorySize, smem_bytes);

    fused_kernel<<<GRID, TPB, smem_bytes>>>(yt, yp, (float*)d_out);
}